// round 3
// baseline (speedup 1.0000x reference)
#include <cuda_runtime.h>
#include <cuda_fp16.h>

#define NN 100000
#define EE 1600000
#define FI 128
#define DD 32
#define GG 1000
#define CC 10
#define BN_EPS 1e-5f

// Scratch (device globals: no allocation allowed)
__device__ __align__(128) float g_p[NN * DD];    // layer-1 projected features (fp32 self-term)
__device__ __align__(128) float g_h[NN * DD];    // layer output h (fp32 self-term)
__device__ __align__(128) __half g_hh[NN * DD];  // fp16 copy for edge gather
__device__ float g_stats[5 * 2 * DD];            // per-BN-layer [sum(32), sumsq(32)]
__device__ float g_pooled[GG * DD];              // global_add_pool accumulator
__device__ int g_deg[NN];                        // in-degree
__device__ int g_row[NN];                        // CSR row offsets
__device__ int g_pos[NN];                        // fill cursor
__device__ int g_csr[EE];                        // src ids grouped by dst
__device__ int g_bsum[128];                      // scan block sums
__device__ int g_boff[128];                      // scan block offsets

// ---------------------------------------------------------------------------
__global__ void k_init() {
    int i = blockIdx.x * blockDim.x + threadIdx.x;
    if (i < GG * DD) g_pooled[i] = 0.f;
    if (i < 5 * 2 * DD) g_stats[i] = 0.f;
    if (i < NN) g_deg[i] = 0;
}

// ---------------------------------------------------------------------------
// CSR build
__global__ __launch_bounds__(256) void k_hist(const int* __restrict__ dst) {
    int e = blockIdx.x * 256 + threadIdx.x;
    if (e < EE) atomicAdd(&g_deg[dst[e]], 1);
}

__global__ __launch_bounds__(256) void k_scan1() {
    int b = blockIdx.x, t = threadIdx.x;
    int lane = t & 31, w = t >> 5;
    int idx0 = b * 1024 + t * 4;
    int v[4];
#pragma unroll
    for (int u = 0; u < 4; u++) v[u] = (idx0 + u < NN) ? g_deg[idx0 + u] : 0;
    int tsum = v[0] + v[1] + v[2] + v[3];
    int incl = tsum;
#pragma unroll
    for (int d = 1; d < 32; d <<= 1) {
        int o = __shfl_up_sync(0xffffffffu, incl, d);
        if (lane >= d) incl += o;
    }
    __shared__ int wsum[8];
    if (lane == 31) wsum[w] = incl;
    __syncthreads();
    int woff = 0;
    for (int i = 0; i < w; i++) woff += wsum[i];
    int run = woff + incl - tsum;
#pragma unroll
    for (int u = 0; u < 4; u++) {
        if (idx0 + u < NN) g_row[idx0 + u] = run;
        run += v[u];
    }
    if (t == 255) g_bsum[b] = woff + incl;
}

// Parallel scan over <=128 block sums (one block, 128 threads)
__global__ void k_scan2(int nblk) {
    int t = threadIdx.x;
    int lane = t & 31, w = t >> 5;
    int v = (t < nblk) ? g_bsum[t] : 0;
    int incl = v;
#pragma unroll
    for (int d = 1; d < 32; d <<= 1) {
        int o = __shfl_up_sync(0xffffffffu, incl, d);
        if (lane >= d) incl += o;
    }
    __shared__ int wsum[4];
    if (lane == 31) wsum[w] = incl;
    __syncthreads();
    int woff = 0;
    for (int i = 0; i < w; i++) woff += wsum[i];
    g_boff[t] = woff + incl - v;  // exclusive
}

__global__ __launch_bounds__(256) void k_scan3() {
    int i = blockIdx.x * 256 + threadIdx.x;
    if (i < NN) {
        int r = g_row[i] + g_boff[i >> 10];
        g_row[i] = r;
        g_pos[i] = r;
    }
}

__global__ __launch_bounds__(256) void k_fill(const int* __restrict__ src,
                                              const int* __restrict__ dst) {
    int e = blockIdx.x * 256 + threadIdx.x;
    if (e < EE) {
        int slot = atomicAdd(&g_pos[dst[e]], 1);
        g_csr[slot] = src[e];
    }
}

// ---------------------------------------------------------------------------
// Layer-1 projection: p = x @ W1a  (N x 128 @ 128 x 32) -> g_p (fp32) + g_hh (fp16)
__global__ __launch_bounds__(256) void k_proj1(const float* __restrict__ x,
                                               const float* __restrict__ W) {
    __shared__ __align__(16) float sW[FI * DD];
    for (int i = threadIdx.x; i < FI * DD; i += 256) sW[i] = W[i];
    __syncthreads();

    int node = blockIdx.x * 256 + threadIdx.x;
    if (node >= NN) return;

    float acc[DD];
#pragma unroll
    for (int j = 0; j < DD; j++) acc[j] = 0.f;

    const float4* xr = (const float4*)(x + (size_t)node * FI);
#pragma unroll 4
    for (int k4 = 0; k4 < FI / 4; k4++) {
        float4 xv = xr[k4];
#pragma unroll
        for (int t = 0; t < 4; t++) {
            float xs = (t == 0) ? xv.x : (t == 1) ? xv.y : (t == 2) ? xv.z : xv.w;
            const float4* wr = (const float4*)&sW[(k4 * 4 + t) * DD];
#pragma unroll
            for (int j4 = 0; j4 < DD / 4; j4++) {
                float4 w = wr[j4];
                acc[j4 * 4 + 0] += xs * w.x;
                acc[j4 * 4 + 1] += xs * w.y;
                acc[j4 * 4 + 2] += xs * w.z;
                acc[j4 * 4 + 3] += xs * w.w;
            }
        }
    }
    float4* pp = (float4*)&g_p[(size_t)node * DD];
#pragma unroll
    for (int j4 = 0; j4 < 8; j4++)
        pp[j4] = make_float4(acc[j4 * 4], acc[j4 * 4 + 1], acc[j4 * 4 + 2], acc[j4 * 4 + 3]);

    __half2 hbuf[DD / 2];
#pragma unroll
    for (int j = 0; j < DD / 2; j++)
        hbuf[j] = __floats2half2_rn(acc[2 * j], acc[2 * j + 1]);
    uint4* hh = (uint4*)&g_hh[(size_t)node * DD];
    const uint4* hb = (const uint4*)hbuf;
#pragma unroll
    for (int j = 0; j < 4; j++) hh[j] = hb[j];
}

// ---------------------------------------------------------------------------
// Layer 1 fused gather+MLP+stats: warp per node, lane = feature.
//   agg = sum p16[src]; t = relu(p[n] + agg + b1a); h = relu(t @ W1b + b1b)
__global__ __launch_bounds__(256) void k_gma1(const float* __restrict__ b1a,
                                              const float* __restrict__ W1b,
                                              const float* __restrict__ b1b) {
    int lane = threadIdx.x & 31;
    int w = threadIdx.x >> 5;

    float wb[DD];
#pragma unroll
    for (int k = 0; k < DD; k++) wb[k] = W1b[k * DD + lane];
    float bal = b1a[lane], bbl = b1b[lane];

    __shared__ float sS[DD], sQ[DD];
    if (threadIdx.x < DD) { sS[threadIdx.x] = 0.f; sQ[threadIdx.x] = 0.f; }
    __syncthreads();

    int warpsTotal = gridDim.x * 8;
    float ls = 0.f, lq = 0.f;

    for (int n = blockIdx.x * 8 + w; n < NN; n += warpsTotal) {
        int base = g_row[n];
        int cnt = g_deg[n];
        float acc = 0.f;
        int i = 0;
        for (; i + 4 <= cnt; i += 4) {
            int s0 = g_csr[base + i + 0];
            int s1 = g_csr[base + i + 1];
            int s2 = g_csr[base + i + 2];
            int s3 = g_csr[base + i + 3];
            float v0 = __half2float(g_hh[(size_t)s0 * DD + lane]);
            float v1 = __half2float(g_hh[(size_t)s1 * DD + lane]);
            float v2 = __half2float(g_hh[(size_t)s2 * DD + lane]);
            float v3 = __half2float(g_hh[(size_t)s3 * DD + lane]);
            acc += (v0 + v1) + (v2 + v3);
        }
        for (; i < cnt; i++) acc += __half2float(g_hh[(size_t)g_csr[base + i] * DD + lane]);

        float t0 = fmaxf(g_p[(size_t)n * DD + lane] + acc + bal, 0.f);
        float hv = bbl;
#pragma unroll
        for (int k = 0; k < DD; k++)
            hv = fmaf(__shfl_sync(0xffffffffu, t0, k), wb[k], hv);
        hv = fmaxf(hv, 0.f);
        g_h[(size_t)n * DD + lane] = hv;
        ls += hv;
        lq += hv * hv;
    }

    atomicAdd(&sS[lane], ls);
    atomicAdd(&sQ[lane], lq);
    __syncthreads();
    if (w == 0) {
        atomicAdd(&g_stats[lane], sS[lane]);
        atomicAdd(&g_stats[DD + lane], sQ[lane]);
    }
}

// h -> fp16 copy (separate pass: next layer gathers need ALL h written first anyway,
// so fold it into the gather kernel's producer side instead: done here cheaply)
__global__ __launch_bounds__(256) void k_h2half() {
    int i = blockIdx.x * 256 + threadIdx.x;  // one thread per 2 features
    if (i < NN * DD / 2) {
        float2 v = ((const float2*)g_h)[i];
        ((__half2*)g_hh)[i] = __floats2half2_rn(v.x, v.y);
    }
}

// ---------------------------------------------------------------------------
// Layers 2-5 fused BN + GIN conv + MLP + stats. Warp per node, lane = feature.
//   raw = h[n] + sum_j h16[j]
//   t   = relu( raw @ (diag(s)Wa) + (1+deg)*(c@Wa) + ba )
//   h'  = relu( t @ Wb + bb );  accumulate stats of h'.
__global__ __launch_bounds__(256) void k_gma(int stats_layer,
                                             const float* __restrict__ gamma,
                                             const float* __restrict__ beta,
                                             const float* __restrict__ Wa,
                                             const float* __restrict__ ba,
                                             const float* __restrict__ Wb,
                                             const float* __restrict__ bb,
                                             int write_half) {
    int lane = threadIdx.x & 31;
    int w = threadIdx.x >> 5;

    __shared__ float sS[DD], sC[DD];
    __shared__ float sSt[DD], sQt[DD];
    const float* st = g_stats + stats_layer * 2 * DD;
    if (threadIdx.x < DD) {
        float m = st[threadIdx.x] * (1.f / NN);
        float v = st[DD + threadIdx.x] * (1.f / NN) - m * m;
        float s = gamma[threadIdx.x] * rsqrtf(v + BN_EPS);
        sS[threadIdx.x] = s;
        sC[threadIdx.x] = beta[threadIdx.x] - m * s;
        sSt[threadIdx.x] = 0.f;
        sQt[threadIdx.x] = 0.f;
    }
    __syncthreads();

    // Register-resident weight columns (column `lane` of each matrix)
    float wa[DD], wb[DD];
    float cbl = 0.f;
#pragma unroll
    for (int k = 0; k < DD; k++) {
        float wv = Wa[k * DD + lane];
        wa[k] = sS[k] * wv;
        cbl = fmaf(sC[k], wv, cbl);
        wb[k] = Wb[k * DD + lane];
    }
    float bal = ba[lane], bbl = bb[lane];

    int warpsTotal = gridDim.x * 8;
    float ls = 0.f, lq = 0.f;

    for (int n = blockIdx.x * 8 + w; n < NN; n += warpsTotal) {
        int base = g_row[n];
        int cnt = g_deg[n];
        float agg = 0.f;
        int i = 0;
        for (; i + 4 <= cnt; i += 4) {
            int s0 = g_csr[base + i + 0];
            int s1 = g_csr[base + i + 1];
            int s2 = g_csr[base + i + 2];
            int s3 = g_csr[base + i + 3];
            float v0 = __half2float(g_hh[(size_t)s0 * DD + lane]);
            float v1 = __half2float(g_hh[(size_t)s1 * DD + lane]);
            float v2 = __half2float(g_hh[(size_t)s2 * DD + lane]);
            float v3 = __half2float(g_hh[(size_t)s3 * DD + lane]);
            agg += (v0 + v1) + (v2 + v3);
        }
        for (; i < cnt; i++) agg += __half2float(g_hh[(size_t)g_csr[base + i] * DD + lane]);

        float raw = g_h[(size_t)n * DD + lane] + agg;

        float acc = fmaf((float)(1 + cnt), cbl, bal);
#pragma unroll
        for (int k = 0; k < DD; k++)
            acc = fmaf(__shfl_sync(0xffffffffu, raw, k), wa[k], acc);
        float t0 = fmaxf(acc, 0.f);

        float hv = bbl;
#pragma unroll
        for (int k = 0; k < DD; k++)
            hv = fmaf(__shfl_sync(0xffffffffu, t0, k), wb[k], hv);
        hv = fmaxf(hv, 0.f);

        g_h[(size_t)n * DD + lane] = hv;
        ls += hv;
        lq += hv * hv;
    }

    atomicAdd(&sSt[lane], ls);
    atomicAdd(&sQt[lane], lq);
    __syncthreads();
    if (w == 0) {
        float* sto = g_stats + (stats_layer + 1) * 2 * DD;
        atomicAdd(&sto[lane], sSt[lane]);
        atomicAdd(&sto[DD + lane], sQt[lane]);
    }
}

// ---------------------------------------------------------------------------
// Segmented global add pool (batch is sorted): warp handles 64 consecutive
// nodes, accumulates in registers while graph id unchanged, flushes on change.
__global__ __launch_bounds__(256) void k_pool(const int* __restrict__ batch,
                                              const float* __restrict__ gamma,
                                              const float* __restrict__ beta) {
    __shared__ float sS[DD], sC[DD];
    const float* st = g_stats + 4 * 2 * DD;
    if (threadIdx.x < DD) {
        float m = st[threadIdx.x] * (1.f / NN);
        float v = st[DD + threadIdx.x] * (1.f / NN) - m * m;
        float s = gamma[threadIdx.x] * rsqrtf(v + BN_EPS);
        sS[threadIdx.x] = s;
        sC[threadIdx.x] = beta[threadIdx.x] - m * s;
    }
    __syncthreads();

    int lane = threadIdx.x & 31;
    int w = threadIdx.x >> 5;
    int wid = blockIdx.x * 8 + w;
    int n0 = wid * 64;
    if (n0 >= NN) return;
    int n1 = min(n0 + 64, NN);

    float s = sS[lane], c = sC[lane];
    int curg = __ldg(&batch[n0]);
    float acc = 0.f;
    for (int n = n0; n < n1; n++) {
        int g = __ldg(&batch[n]);
        if (g != curg) {
            atomicAdd(&g_pooled[curg * DD + lane], acc);
            acc = 0.f;
            curg = g;
        }
        acc = fmaf(s, g_h[(size_t)n * DD + lane], acc + c);
    }
    atomicAdd(&g_pooled[curg * DD + lane], acc);
}

// ---------------------------------------------------------------------------
// Head: relu(pooled@fc1+b1) @ fc2 + b2, log_softmax. One thread per graph.
__global__ __launch_bounds__(256) void k_head(const float* __restrict__ fc1w,
                                              const float* __restrict__ fc1b,
                                              const float* __restrict__ fc2w,
                                              const float* __restrict__ fc2b,
                                              float* __restrict__ out) {
    __shared__ float sW1[DD * DD], sW2[DD * CC], sb1[DD], sb2[CC];
    for (int i = threadIdx.x; i < DD * DD; i += 256) sW1[i] = fc1w[i];
    for (int i = threadIdx.x; i < DD * CC; i += 256) sW2[i] = fc2w[i];
    if (threadIdx.x < DD) sb1[threadIdx.x] = fc1b[threadIdx.x];
    if (threadIdx.x < CC) sb2[threadIdx.x] = fc2b[threadIdx.x];
    __syncthreads();

    int g = blockIdx.x * 256 + threadIdx.x;
    if (g >= GG) return;

    float pv[DD];
    const float4* pr = (const float4*)&g_pooled[g * DD];
#pragma unroll
    for (int j4 = 0; j4 < 8; j4++) {
        float4 t = pr[j4];
        pv[j4 * 4 + 0] = t.x; pv[j4 * 4 + 1] = t.y;
        pv[j4 * 4 + 2] = t.z; pv[j4 * 4 + 3] = t.w;
    }
    float u[DD];
#pragma unroll
    for (int j = 0; j < DD; j++) u[j] = sb1[j];
#pragma unroll 4
    for (int k = 0; k < DD; k++) {
        float pk = pv[k];
#pragma unroll
        for (int j = 0; j < DD; j++) u[j] += pk * sW1[k * DD + j];
    }
#pragma unroll
    for (int j = 0; j < DD; j++) u[j] = fmaxf(u[j], 0.f);

    float lg[CC];
#pragma unroll
    for (int c = 0; c < CC; c++) lg[c] = sb2[c];
#pragma unroll 4
    for (int j = 0; j < DD; j++) {
        float uj = u[j];
#pragma unroll
        for (int c = 0; c < CC; c++) lg[c] += uj * sW2[j * CC + c];
    }
    float mx = lg[0];
#pragma unroll
    for (int c = 1; c < CC; c++) mx = fmaxf(mx, lg[c]);
    float se = 0.f;
#pragma unroll
    for (int c = 0; c < CC; c++) se += expf(lg[c] - mx);
    float lse = mx + logf(se);
#pragma unroll
    for (int c = 0; c < CC; c++) out[g * CC + c] = lg[c] - lse;
}

// ---------------------------------------------------------------------------
extern "C" void kernel_launch(void* const* d_in, const int* in_sizes, int n_in,
                              void* d_out, int out_size) {
    const float* x     = (const float*)d_in[0];
    const int*   ei    = (const int*)d_in[1];
    const int*   batch = (const int*)d_in[2];
    const float* W1a   = (const float*)d_in[3];
    const float* b1a   = (const float*)d_in[4];
    const float* W1b   = (const float*)d_in[5];
    const float* b1b   = (const float*)d_in[6];
    const float* Wa    = (const float*)d_in[7];
    const float* ba    = (const float*)d_in[8];
    const float* Wb    = (const float*)d_in[9];
    const float* bb    = (const float*)d_in[10];
    const float* gamma = (const float*)d_in[11];
    const float* beta  = (const float*)d_in[12];
    const float* fc1w  = (const float*)d_in[13];
    const float* fc1b  = (const float*)d_in[14];
    const float* fc2w  = (const float*)d_in[15];
    const float* fc2b  = (const float*)d_in[16];
    float* out = (float*)d_out;

    const int* src = ei;        // row 0
    const int* dst = ei + EE;   // row 1

    const int NB = (NN + 255) / 256;          // 391
    const int EB = EE / 256;                  // 6250
    const int SCAN_BLK = (NN + 1023) / 1024;  // 98
    const int GMA_BLK = 1480;
    const int HB = (NN * DD / 2 + 255) / 256;
    const int PB = ((NN + 63) / 64 + 7) / 8;

    k_init<<<NB, 256>>>();

    // CSR build (dst-grouped edge list)
    k_hist<<<EB, 256>>>(dst);
    k_scan1<<<SCAN_BLK, 256>>>();
    k_scan2<<<1, 128>>>(SCAN_BLK);
    k_scan3<<<NB, 256>>>();
    k_fill<<<EB, 256>>>(src, dst);

    // Layer 1
    k_proj1<<<NB, 256>>>(x, W1a);
    k_gma1<<<GMA_BLK, 256>>>(b1a, W1b, b1b);

    // Layers 2-5 (BN folded; gather in h-space)
    for (int i = 0; i < 4; i++) {
        k_h2half<<<HB, 256>>>();
        k_gma<<<GMA_BLK, 256>>>(i, gamma + i * DD, beta + i * DD,
                                Wa + i * DD * DD, ba + i * DD,
                                Wb + i * DD * DD, bb + i * DD, i < 3);
    }

    // Pool (applies BN layer 5) + head
    k_pool<<<PB, 256>>>(batch, gamma + 4 * DD, beta + 4 * DD);
    k_head<<<(GG + 255) / 256, 256>>>(fc1w, fc1b, fc2w, fc2b, out);
}

// round 4
// speedup vs baseline: 1.4847x; 1.4847x over previous
#include <cuda_runtime.h>

#define NN 100000
#define EE 1600000
#define FI 128
#define DD 32
#define GG 1000
#define CC 10
#define BN_EPS 1e-5f

// Scratch (device globals: no allocation allowed)
__device__ __align__(128) float g_p[NN * DD];   // projected features per node
__device__ __align__(128) float g_h[NN * DD];   // layer output (pre-BN)
__device__ float g_stats[5 * 2 * DD];           // per-BN-layer [sum(32), sumsq(32)]
__device__ float g_pooled[GG * DD];             // global_add_pool accumulator
__device__ int g_deg[NN];                       // in-degree
__device__ int g_row[NN];                       // CSR row offsets
__device__ int g_pos[NN];                       // fill cursor
__device__ int g_csr[EE];                       // src ids grouped by dst
__device__ int g_bsum[128];                     // scan block sums
__device__ int g_boff[128];                     // scan block offsets

// ---------------------------------------------------------------------------
__global__ void k_init() {
    int i = blockIdx.x * blockDim.x + threadIdx.x;
    if (i < GG * DD) g_pooled[i] = 0.f;
    if (i < 5 * 2 * DD) g_stats[i] = 0.f;
    if (i < NN) g_deg[i] = 0;
}

// ---------------------------------------------------------------------------
// CSR build
__global__ __launch_bounds__(256) void k_hist(const int* __restrict__ dst) {
    int e = blockIdx.x * 256 + threadIdx.x;
    if (e < EE) atomicAdd(&g_deg[dst[e]], 1);
}

__global__ __launch_bounds__(256) void k_scan1() {
    int b = blockIdx.x, t = threadIdx.x;
    int lane = t & 31, w = t >> 5;
    int idx0 = b * 1024 + t * 4;
    int v[4];
#pragma unroll
    for (int u = 0; u < 4; u++) v[u] = (idx0 + u < NN) ? g_deg[idx0 + u] : 0;
    int tsum = v[0] + v[1] + v[2] + v[3];
    int incl = tsum;
#pragma unroll
    for (int d = 1; d < 32; d <<= 1) {
        int o = __shfl_up_sync(0xffffffffu, incl, d);
        if (lane >= d) incl += o;
    }
    __shared__ int wsum[8];
    if (lane == 31) wsum[w] = incl;
    __syncthreads();
    int woff = 0;
    for (int i = 0; i < w; i++) woff += wsum[i];
    int run = woff + incl - tsum;
#pragma unroll
    for (int u = 0; u < 4; u++) {
        if (idx0 + u < NN) g_row[idx0 + u] = run;
        run += v[u];
    }
    if (t == 255) g_bsum[b] = woff + incl;
}

// Parallel scan over <=128 block sums (one block, 128 threads)
__global__ void k_scan2(int nblk) {
    int t = threadIdx.x;
    int lane = t & 31, w = t >> 5;
    int v = (t < nblk) ? g_bsum[t] : 0;
    int incl = v;
#pragma unroll
    for (int d = 1; d < 32; d <<= 1) {
        int o = __shfl_up_sync(0xffffffffu, incl, d);
        if (lane >= d) incl += o;
    }
    __shared__ int wsum[4];
    if (lane == 31) wsum[w] = incl;
    __syncthreads();
    int woff = 0;
    for (int i = 0; i < w; i++) woff += wsum[i];
    g_boff[t] = woff + incl - v;  // exclusive
}

__global__ __launch_bounds__(256) void k_scan3() {
    int i = blockIdx.x * 256 + threadIdx.x;
    if (i < NN) {
        int r = g_row[i] + g_boff[i >> 10];
        g_row[i] = r;
        g_pos[i] = r;
    }
}

__global__ __launch_bounds__(256) void k_fill(const int* __restrict__ src,
                                              const int* __restrict__ dst) {
    int e = blockIdx.x * 256 + threadIdx.x;
    if (e < EE) {
        int slot = atomicAdd(&g_pos[dst[e]], 1);
        g_csr[slot] = src[e];
    }
}

// ---------------------------------------------------------------------------
// Layer-1 projection: p = x @ W1a  (N x 128 @ 128 x 32)
__global__ __launch_bounds__(256) void k_proj1(const float* __restrict__ x,
                                               const float* __restrict__ W) {
    __shared__ __align__(16) float sW[FI * DD];
    for (int i = threadIdx.x; i < FI * DD; i += 256) sW[i] = W[i];
    __syncthreads();

    int node = blockIdx.x * 256 + threadIdx.x;
    if (node >= NN) return;

    float acc[DD];
#pragma unroll
    for (int j = 0; j < DD; j++) acc[j] = 0.f;

    const float4* xr = (const float4*)(x + (size_t)node * FI);
#pragma unroll 4
    for (int k4 = 0; k4 < FI / 4; k4++) {
        float4 xv = xr[k4];
#pragma unroll
        for (int t = 0; t < 4; t++) {
            float xs = (t == 0) ? xv.x : (t == 1) ? xv.y : (t == 2) ? xv.z : xv.w;
            const float4* wr = (const float4*)&sW[(k4 * 4 + t) * DD];
#pragma unroll
            for (int j4 = 0; j4 < DD / 4; j4++) {
                float4 w = wr[j4];
                acc[j4 * 4 + 0] += xs * w.x;
                acc[j4 * 4 + 1] += xs * w.y;
                acc[j4 * 4 + 2] += xs * w.z;
                acc[j4 * 4 + 3] += xs * w.w;
            }
        }
    }
    float4* pp = (float4*)&g_p[(size_t)node * DD];
#pragma unroll
    for (int j4 = 0; j4 < 8; j4++)
        pp[j4] = make_float4(acc[j4 * 4], acc[j4 * 4 + 1], acc[j4 * 4 + 2], acc[j4 * 4 + 3]);
}

// ---------------------------------------------------------------------------
// Layers 2-5 projection with folded BatchNorm:
//   bn(h) = s*h + c;  p = h @ (diag(s)Wa) + c@Wa
__global__ __launch_bounds__(256) void k_proj(int stats_layer,
                                              const float* __restrict__ gamma,
                                              const float* __restrict__ beta,
                                              const float* __restrict__ Wa) {
    __shared__ float sS[DD], sC[DD], sCB[DD];
    __shared__ __align__(16) float sW[DD * DD];
    const float* st = g_stats + stats_layer * 2 * DD;
    if (threadIdx.x < DD) {
        float m = st[threadIdx.x] * (1.f / NN);
        float v = st[DD + threadIdx.x] * (1.f / NN) - m * m;
        float s = gamma[threadIdx.x] * rsqrtf(v + BN_EPS);
        sS[threadIdx.x] = s;
        sC[threadIdx.x] = beta[threadIdx.x] - m * s;
    }
    __syncthreads();
    for (int i = threadIdx.x; i < DD * DD; i += 256) sW[i] = sS[i >> 5] * Wa[i];
    __syncthreads();
    if (threadIdx.x < DD) {
        float c = 0.f;
#pragma unroll
        for (int f = 0; f < DD; f++) c += sC[f] * Wa[f * DD + threadIdx.x];
        sCB[threadIdx.x] = c;
    }
    __syncthreads();

    int node = blockIdx.x * 256 + threadIdx.x;
    if (node >= NN) return;

    float hv[DD];
    const float4* hr = (const float4*)&g_h[(size_t)node * DD];
#pragma unroll
    for (int j4 = 0; j4 < 8; j4++) {
        float4 t = hr[j4];
        hv[j4 * 4 + 0] = t.x; hv[j4 * 4 + 1] = t.y;
        hv[j4 * 4 + 2] = t.z; hv[j4 * 4 + 3] = t.w;
    }
    float acc[DD];
#pragma unroll
    for (int j = 0; j < DD; j++) acc[j] = sCB[j];
#pragma unroll 4
    for (int k = 0; k < DD; k++) {
        float hk = hv[k];
        const float4* wr = (const float4*)&sW[k * DD];
#pragma unroll
        for (int j4 = 0; j4 < 8; j4++) {
            float4 w = wr[j4];
            acc[j4 * 4 + 0] += hk * w.x;
            acc[j4 * 4 + 1] += hk * w.y;
            acc[j4 * 4 + 2] += hk * w.z;
            acc[j4 * 4 + 3] += hk * w.w;
        }
    }
    float4* pp = (float4*)&g_p[(size_t)node * DD];
#pragma unroll
    for (int j4 = 0; j4 < 8; j4++)
        pp[j4] = make_float4(acc[j4 * 4], acc[j4 * 4 + 1], acc[j4 * 4 + 2], acc[j4 * 4 + 3]);
}

// ---------------------------------------------------------------------------
// Fused gather + MLP + stats. One warp per node.
// Lane layout: sub = lane>>3 (edge subgroup 0..3), quad = lane&7 (float4 chunk).
// Each lane loads float4 -> one warp-load covers 4 edges (512B).
//   agg = sum_{e} p[src_e];  t = relu(p[n] + agg + ba);  h = relu(t @ Wb + bb)
__global__ __launch_bounds__(256) void k_gma(const float* __restrict__ ba,
                                             const float* __restrict__ Wb,
                                             const float* __restrict__ bb,
                                             int stats_layer) {
    __shared__ __align__(16) float sW[DD * DD];
    __shared__ float sba4[DD], sbb[DD], sS[DD], sQ[DD];
    for (int i = threadIdx.x; i < DD * DD; i += 256) sW[i] = Wb[i];
    if (threadIdx.x < DD) {
        sba4[threadIdx.x] = ba[threadIdx.x];
        sbb[threadIdx.x] = bb[threadIdx.x];
        sS[threadIdx.x] = 0.f;
        sQ[threadIdx.x] = 0.f;
    }
    __syncthreads();

    int lane = threadIdx.x & 31;
    int w = threadIdx.x >> 5;
    int sub = lane >> 3;
    int quad = lane & 7;
    const unsigned FULL = 0xffffffffu;

    int warpsTotal = gridDim.x * 8;
    float ls = 0.f, lq = 0.f;

    for (int n = blockIdx.x * 8 + w; n < NN; n += warpsTotal) {
        int base = g_row[n];
        int cnt = g_deg[n];
        float4 a4 = make_float4(0.f, 0.f, 0.f, 0.f);
        int i = 0;
        // 16 edges per iteration: 4 index loads + 4 float4 loads per lane
        for (; i + 16 <= cnt; i += 16) {
            int s0 = g_csr[base + i + sub];
            int s1 = g_csr[base + i + 4 + sub];
            int s2 = g_csr[base + i + 8 + sub];
            int s3 = g_csr[base + i + 12 + sub];
            float4 v0 = *(const float4*)&g_p[(size_t)s0 * DD + quad * 4];
            float4 v1 = *(const float4*)&g_p[(size_t)s1 * DD + quad * 4];
            float4 v2 = *(const float4*)&g_p[(size_t)s2 * DD + quad * 4];
            float4 v3 = *(const float4*)&g_p[(size_t)s3 * DD + quad * 4];
            a4.x += (v0.x + v1.x) + (v2.x + v3.x);
            a4.y += (v0.y + v1.y) + (v2.y + v3.y);
            a4.z += (v0.z + v1.z) + (v2.z + v3.z);
            a4.w += (v0.w + v1.w) + (v2.w + v3.w);
        }
        for (; i + 4 <= cnt; i += 4) {
            int s0 = g_csr[base + i + sub];
            float4 v0 = *(const float4*)&g_p[(size_t)s0 * DD + quad * 4];
            a4.x += v0.x; a4.y += v0.y; a4.z += v0.z; a4.w += v0.w;
        }
        if (i + sub < cnt) {
            int s0 = g_csr[base + i + sub];
            float4 v0 = *(const float4*)&g_p[(size_t)s0 * DD + quad * 4];
            a4.x += v0.x; a4.y += v0.y; a4.z += v0.z; a4.w += v0.w;
        }
        // reduce across the 4 edge subgroups (xor orbit {l, l^8, l^16, l^24})
        a4.x += __shfl_xor_sync(FULL, a4.x, 8);
        a4.y += __shfl_xor_sync(FULL, a4.y, 8);
        a4.z += __shfl_xor_sync(FULL, a4.z, 8);
        a4.w += __shfl_xor_sync(FULL, a4.w, 8);
        a4.x += __shfl_xor_sync(FULL, a4.x, 16);
        a4.y += __shfl_xor_sync(FULL, a4.y, 16);
        a4.z += __shfl_xor_sync(FULL, a4.z, 16);
        a4.w += __shfl_xor_sync(FULL, a4.w, 16);

        // self term + bias + relu (per-quad float4)
        float4 self = *(const float4*)&g_p[(size_t)n * DD + quad * 4];
        const float4 b4 = *(const float4*)&sba4[quad * 4];
        float4 t4;
        t4.x = fmaxf(a4.x + self.x + b4.x, 0.f);
        t4.y = fmaxf(a4.y + self.y + b4.y, 0.f);
        t4.z = fmaxf(a4.z + self.z + b4.z, 0.f);
        t4.w = fmaxf(a4.w + self.w + b4.w, 0.f);

        // matvec: feature k lives in component k&3 of lane k>>2
        float hv = sbb[lane];
#pragma unroll
        for (int k = 0; k < DD; k++) {
            float comp = ((k & 3) == 0) ? t4.x : ((k & 3) == 1) ? t4.y
                       : ((k & 3) == 2) ? t4.z : t4.w;
            float tk = __shfl_sync(FULL, comp, k >> 2);
            hv = fmaf(tk, sW[k * DD + lane], hv);
        }
        hv = fmaxf(hv, 0.f);
        g_h[(size_t)n * DD + lane] = hv;
        ls += hv;
        lq += hv * hv;
    }

    atomicAdd(&sS[lane], ls);
    atomicAdd(&sQ[lane], lq);
    __syncthreads();
    if (w == 0) {
        float* st = g_stats + stats_layer * 2 * DD;
        atomicAdd(&st[lane], sS[lane]);
        atomicAdd(&st[DD + lane], sQ[lane]);
    }
}

// ---------------------------------------------------------------------------
// Segmented global add pool (batch is sorted): warp handles 64 consecutive
// nodes, accumulates in registers while graph id unchanged, flushes on change.
__global__ __launch_bounds__(256) void k_pool(const int* __restrict__ batch,
                                              const float* __restrict__ gamma,
                                              const float* __restrict__ beta) {
    __shared__ float sS[DD], sC[DD];
    const float* st = g_stats + 4 * 2 * DD;
    if (threadIdx.x < DD) {
        float m = st[threadIdx.x] * (1.f / NN);
        float v = st[DD + threadIdx.x] * (1.f / NN) - m * m;
        float s = gamma[threadIdx.x] * rsqrtf(v + BN_EPS);
        sS[threadIdx.x] = s;
        sC[threadIdx.x] = beta[threadIdx.x] - m * s;
    }
    __syncthreads();

    int lane = threadIdx.x & 31;
    int w = threadIdx.x >> 5;
    int wid = blockIdx.x * 8 + w;
    int n0 = wid * 64;
    if (n0 >= NN) return;
    int n1 = min(n0 + 64, NN);

    float s = sS[lane], c = sC[lane];
    int curg = __ldg(&batch[n0]);
    float acc = 0.f;
    for (int n = n0; n < n1; n++) {
        int g = __ldg(&batch[n]);
        if (g != curg) {
            atomicAdd(&g_pooled[curg * DD + lane], acc);
            acc = 0.f;
            curg = g;
        }
        acc = fmaf(s, g_h[(size_t)n * DD + lane], acc + c);
    }
    atomicAdd(&g_pooled[curg * DD + lane], acc);
}

// ---------------------------------------------------------------------------
// Head: relu(pooled@fc1+b1) @ fc2 + b2, log_softmax. One thread per graph.
__global__ __launch_bounds__(256) void k_head(const float* __restrict__ fc1w,
                                              const float* __restrict__ fc1b,
                                              const float* __restrict__ fc2w,
                                              const float* __restrict__ fc2b,
                                              float* __restrict__ out) {
    __shared__ float sW1[DD * DD], sW2[DD * CC], sb1[DD], sb2[CC];
    for (int i = threadIdx.x; i < DD * DD; i += 256) sW1[i] = fc1w[i];
    for (int i = threadIdx.x; i < DD * CC; i += 256) sW2[i] = fc2w[i];
    if (threadIdx.x < DD) sb1[threadIdx.x] = fc1b[threadIdx.x];
    if (threadIdx.x < CC) sb2[threadIdx.x] = fc2b[threadIdx.x];
    __syncthreads();

    int g = blockIdx.x * 256 + threadIdx.x;
    if (g >= GG) return;

    float pv[DD];
    const float4* pr = (const float4*)&g_pooled[g * DD];
#pragma unroll
    for (int j4 = 0; j4 < 8; j4++) {
        float4 t = pr[j4];
        pv[j4 * 4 + 0] = t.x; pv[j4 * 4 + 1] = t.y;
        pv[j4 * 4 + 2] = t.z; pv[j4 * 4 + 3] = t.w;
    }
    float u[DD];
#pragma unroll
    for (int j = 0; j < DD; j++) u[j] = sb1[j];
#pragma unroll 4
    for (int k = 0; k < DD; k++) {
        float pk = pv[k];
#pragma unroll
        for (int j = 0; j < DD; j++) u[j] += pk * sW1[k * DD + j];
    }
#pragma unroll
    for (int j = 0; j < DD; j++) u[j] = fmaxf(u[j], 0.f);

    float lg[CC];
#pragma unroll
    for (int c = 0; c < CC; c++) lg[c] = sb2[c];
#pragma unroll 4
    for (int j = 0; j < DD; j++) {
        float uj = u[j];
#pragma unroll
        for (int c = 0; c < CC; c++) lg[c] += uj * sW2[j * CC + c];
    }
    float mx = lg[0];
#pragma unroll
    for (int c = 1; c < CC; c++) mx = fmaxf(mx, lg[c]);
    float se = 0.f;
#pragma unroll
    for (int c = 0; c < CC; c++) se += expf(lg[c] - mx);
    float lse = mx + logf(se);
#pragma unroll
    for (int c = 0; c < CC; c++) out[g * CC + c] = lg[c] - lse;
}

// ---------------------------------------------------------------------------
extern "C" void kernel_launch(void* const* d_in, const int* in_sizes, int n_in,
                              void* d_out, int out_size) {
    const float* x     = (const float*)d_in[0];
    const int*   ei    = (const int*)d_in[1];
    const int*   batch = (const int*)d_in[2];
    const float* W1a   = (const float*)d_in[3];
    const float* b1a   = (const float*)d_in[4];
    const float* W1b   = (const float*)d_in[5];
    const float* b1b   = (const float*)d_in[6];
    const float* Wa    = (const float*)d_in[7];
    const float* ba    = (const float*)d_in[8];
    const float* Wb    = (const float*)d_in[9];
    const float* bb    = (const float*)d_in[10];
    const float* gamma = (const float*)d_in[11];
    const float* beta  = (const float*)d_in[12];
    const float* fc1w  = (const float*)d_in[13];
    const float* fc1b  = (const float*)d_in[14];
    const float* fc2w  = (const float*)d_in[15];
    const float* fc2b  = (const float*)d_in[16];
    float* out = (float*)d_out;

    const int* src = ei;        // row 0
    const int* dst = ei + EE;   // row 1

    const int NB = (NN + 255) / 256;          // 391
    const int EB = EE / 256;                  // 6250
    const int SCAN_BLK = (NN + 1023) / 1024;  // 98
    const int GMA_BLK = 1480;
    const int PB = ((NN + 63) / 64 + 7) / 8;

    k_init<<<NB, 256>>>();

    // CSR build (dst-grouped edge list)
    k_hist<<<EB, 256>>>(dst);
    k_scan1<<<SCAN_BLK, 256>>>();
    k_scan2<<<1, 128>>>(SCAN_BLK);
    k_scan3<<<NB, 256>>>();
    k_fill<<<EB, 256>>>(src, dst);

    // Layer 1 (GIN F->D->D, relu; stats for BN 0)
    k_proj1<<<NB, 256>>>(x, W1a);
    k_gma<<<GMA_BLK, 256>>>(b1a, W1b, b1b, 0);

    // Layers 2-5 (BN folded into projection)
    for (int i = 0; i < 4; i++) {
        k_proj<<<NB, 256>>>(i, gamma + i * DD, beta + i * DD, Wa + i * DD * DD);
        k_gma<<<GMA_BLK, 256>>>(ba + i * DD, Wb + i * DD * DD, bb + i * DD, i + 1);
    }

    // Pool (applies BN layer 5) + head
    k_pool<<<PB, 256>>>(batch, gamma + 4 * DD, beta + 4 * DD);
    k_head<<<(GG + 255) / 256, 256>>>(fc1w, fc1b, fc2w, fc2b, out);
}

// round 6
// speedup vs baseline: 1.6143x; 1.0873x over previous
#include <cuda_runtime.h>

#define NN 100000
#define EE 1600000
#define FI 128
#define DD 32
#define GG 1000
#define CC 10
#define BN_EPS 1e-5f

// Scratch (device globals: no allocation allowed)
__device__ __align__(128) float g_p[NN * DD];   // projected features per node
__device__ __align__(128) float g_h[NN * DD];   // layer output (pre-BN)
__device__ float g_stats[5 * 2 * DD];           // per-BN-layer [sum(32), sumsq(32)]
__device__ float g_pooled[GG * DD];             // global_add_pool accumulator
__device__ int g_deg[NN];                       // in-degree
__device__ int g_row[NN];                       // CSR row offsets
__device__ int g_pos[NN];                       // fill cursor
__device__ int g_csr[EE];                       // src ids grouped by dst
__device__ int g_bsum[128];                     // scan block sums

// ---------------------------------------------------------------------------
// Layer-1 projection: p = x @ W1a  (N x 128 @ 128 x 32). Also inits scratch.
__global__ __launch_bounds__(256) void k_proj1(const float* __restrict__ x,
                                               const float* __restrict__ W) {
    __shared__ __align__(16) float sW[FI * DD];
    for (int i = threadIdx.x; i < FI * DD; i += 256) sW[i] = W[i];

    int node = blockIdx.x * 256 + threadIdx.x;
    // init scratch (ordering vs later kernels is by launch order, not intra-kernel)
    if (node < NN) g_deg[node] = 0;
    if (node < GG * DD) g_pooled[node] = 0.f;
    if (node < 5 * 2 * DD) g_stats[node] = 0.f;
    __syncthreads();

    if (node >= NN) return;

    float acc[DD];
#pragma unroll
    for (int j = 0; j < DD; j++) acc[j] = 0.f;

    const float4* xr = (const float4*)(x + (size_t)node * FI);
#pragma unroll 4
    for (int k4 = 0; k4 < FI / 4; k4++) {
        float4 xv = xr[k4];
#pragma unroll
        for (int t = 0; t < 4; t++) {
            float xs = (t == 0) ? xv.x : (t == 1) ? xv.y : (t == 2) ? xv.z : xv.w;
            const float4* wr = (const float4*)&sW[(k4 * 4 + t) * DD];
#pragma unroll
            for (int j4 = 0; j4 < DD / 4; j4++) {
                float4 w = wr[j4];
                acc[j4 * 4 + 0] += xs * w.x;
                acc[j4 * 4 + 1] += xs * w.y;
                acc[j4 * 4 + 2] += xs * w.z;
                acc[j4 * 4 + 3] += xs * w.w;
            }
        }
    }
    float4* pp = (float4*)&g_p[(size_t)node * DD];
#pragma unroll
    for (int j4 = 0; j4 < 8; j4++)
        pp[j4] = make_float4(acc[j4 * 4], acc[j4 * 4 + 1], acc[j4 * 4 + 2], acc[j4 * 4 + 3]);
}

// ---------------------------------------------------------------------------
// CSR build
__global__ __launch_bounds__(256) void k_hist(const int* __restrict__ dst) {
    int e = blockIdx.x * 256 + threadIdx.x;
    if (e < EE) atomicAdd(&g_deg[dst[e]], 1);
}

__global__ __launch_bounds__(256) void k_scan1() {
    int b = blockIdx.x, t = threadIdx.x;
    int lane = t & 31, w = t >> 5;
    int idx0 = b * 1024 + t * 4;
    int v[4];
#pragma unroll
    for (int u = 0; u < 4; u++) v[u] = (idx0 + u < NN) ? g_deg[idx0 + u] : 0;
    int tsum = v[0] + v[1] + v[2] + v[3];
    int incl = tsum;
#pragma unroll
    for (int d = 1; d < 32; d <<= 1) {
        int o = __shfl_up_sync(0xffffffffu, incl, d);
        if (lane >= d) incl += o;
    }
    __shared__ int wsum[8];
    if (lane == 31) wsum[w] = incl;
    __syncthreads();
    int woff = 0;
    for (int i = 0; i < w; i++) woff += wsum[i];
    int run = woff + incl - tsum;
#pragma unroll
    for (int u = 0; u < 4; u++) {
        if (idx0 + u < NN) g_row[idx0 + u] = run;
        run += v[u];
    }
    if (t == 255) g_bsum[b] = woff + incl;
}

// Merged scan2+scan3: block b covers ids [b*256,(b+1)*256) which lie inside
// chunk = b>>2 of scan1; offset = sum of g_bsum[0..chunk-1], computed in-block.
__global__ __launch_bounds__(256) void k_scan23() {
    __shared__ int part[8];
    __shared__ int sOff;
    int t = threadIdx.x;
    int lane = t & 31, w = t >> 5;
    int chunk = blockIdx.x >> 2;
    int v = (t < chunk && t < 128) ? g_bsum[t] : 0;
#pragma unroll
    for (int d = 16; d >= 1; d >>= 1) v += __shfl_xor_sync(0xffffffffu, v, d);
    if (lane == 0) part[w] = v;
    __syncthreads();
    if (t == 0) {
        int s = 0;
#pragma unroll
        for (int i = 0; i < 8; i++) s += part[i];
        sOff = s;
    }
    __syncthreads();
    int i = blockIdx.x * 256 + t;
    if (i < NN) {
        int r = g_row[i] + sOff;
        g_row[i] = r;
        g_pos[i] = r;
    }
}

__global__ __launch_bounds__(256) void k_fill(const int* __restrict__ src,
                                              const int* __restrict__ dst) {
    int e = blockIdx.x * 256 + threadIdx.x;
    if (e < EE) {
        int slot = atomicAdd(&g_pos[dst[e]], 1);
        g_csr[slot] = src[e];
    }
}

// ---------------------------------------------------------------------------
// Layers 2-5 projection with folded BatchNorm:
//   bn(h) = s*h + c;  p = h @ (diag(s)Wa) + c@Wa
__global__ __launch_bounds__(256) void k_proj(int stats_layer,
                                              const float* __restrict__ gamma,
                                              const float* __restrict__ beta,
                                              const float* __restrict__ Wa) {
    __shared__ float sS[DD], sC[DD], sCB[DD];
    __shared__ __align__(16) float sW[DD * DD];
    const float* st = g_stats + stats_layer * 2 * DD;
    if (threadIdx.x < DD) {
        float m = st[threadIdx.x] * (1.f / NN);
        float v = st[DD + threadIdx.x] * (1.f / NN) - m * m;
        float s = gamma[threadIdx.x] * rsqrtf(v + BN_EPS);
        sS[threadIdx.x] = s;
        sC[threadIdx.x] = beta[threadIdx.x] - m * s;
    }
    __syncthreads();
    for (int i = threadIdx.x; i < DD * DD; i += 256) sW[i] = sS[i >> 5] * Wa[i];
    __syncthreads();
    if (threadIdx.x < DD) {
        float c = 0.f;
#pragma unroll
        for (int f = 0; f < DD; f++) c += sC[f] * Wa[f * DD + threadIdx.x];
        sCB[threadIdx.x] = c;
    }
    __syncthreads();

    int node = blockIdx.x * 256 + threadIdx.x;
    if (node >= NN) return;

    float hv[DD];
    const float4* hr = (const float4*)&g_h[(size_t)node * DD];
#pragma unroll
    for (int j4 = 0; j4 < 8; j4++) {
        float4 t = hr[j4];
        hv[j4 * 4 + 0] = t.x; hv[j4 * 4 + 1] = t.y;
        hv[j4 * 4 + 2] = t.z; hv[j4 * 4 + 3] = t.w;
    }
    float acc[DD];
#pragma unroll
    for (int j = 0; j < DD; j++) acc[j] = sCB[j];
#pragma unroll 4
    for (int k = 0; k < DD; k++) {
        float hk = hv[k];
        const float4* wr = (const float4*)&sW[k * DD];
#pragma unroll
        for (int j4 = 0; j4 < 8; j4++) {
            float4 w = wr[j4];
            acc[j4 * 4 + 0] += hk * w.x;
            acc[j4 * 4 + 1] += hk * w.y;
            acc[j4 * 4 + 2] += hk * w.z;
            acc[j4 * 4 + 3] += hk * w.w;
        }
    }
    float4* pp = (float4*)&g_p[(size_t)node * DD];
#pragma unroll
    for (int j4 = 0; j4 < 8; j4++)
        pp[j4] = make_float4(acc[j4 * 4], acc[j4 * 4 + 1], acc[j4 * 4 + 2], acc[j4 * 4 + 3]);
}

// ---------------------------------------------------------------------------
// Fused gather + MLP + stats. One warp per node.
// Lane layout: sub = lane>>3 (edge subgroup 0..3), quad = lane&7 (float4 chunk).
// Gather: each lane loads float4 -> one warp-load covers 4 edges (512B).
// MLP matvec: t staged in per-warp smem; broadcast LDS.128 reads against a
// register-resident Wb column (no SHFL chain).
__global__ __launch_bounds__(256) void k_gma(const float* __restrict__ ba,
                                             const float* __restrict__ Wb,
                                             const float* __restrict__ bb,
                                             int stats_layer) {
    __shared__ __align__(16) float sT[8][DD];   // per-warp t vector
    __shared__ float sba4[DD], sS[DD], sQ[DD];
    int lane = threadIdx.x & 31;
    int w = threadIdx.x >> 5;

    float wb[DD];   // column `lane` of Wb
#pragma unroll
    for (int k = 0; k < DD; k++) wb[k] = Wb[k * DD + lane];
    float bbl = bb[lane];

    if (threadIdx.x < DD) {
        sba4[threadIdx.x] = ba[threadIdx.x];
        sS[threadIdx.x] = 0.f;
        sQ[threadIdx.x] = 0.f;
    }
    __syncthreads();

    int sub = lane >> 3;
    int quad = lane & 7;
    const unsigned FULL = 0xffffffffu;

    int warpsTotal = gridDim.x * 8;
    float ls = 0.f, lq = 0.f;

    for (int n = blockIdx.x * 8 + w; n < NN; n += warpsTotal) {
        int base = g_row[n];
        int cnt = g_deg[n];
        float4 a4 = make_float4(0.f, 0.f, 0.f, 0.f);
        int i = 0;
        for (; i + 16 <= cnt; i += 16) {
            int s0 = g_csr[base + i + sub];
            int s1 = g_csr[base + i + 4 + sub];
            int s2 = g_csr[base + i + 8 + sub];
            int s3 = g_csr[base + i + 12 + sub];
            float4 v0 = *(const float4*)&g_p[(size_t)s0 * DD + quad * 4];
            float4 v1 = *(const float4*)&g_p[(size_t)s1 * DD + quad * 4];
            float4 v2 = *(const float4*)&g_p[(size_t)s2 * DD + quad * 4];
            float4 v3 = *(const float4*)&g_p[(size_t)s3 * DD + quad * 4];
            a4.x += (v0.x + v1.x) + (v2.x + v3.x);
            a4.y += (v0.y + v1.y) + (v2.y + v3.y);
            a4.z += (v0.z + v1.z) + (v2.z + v3.z);
            a4.w += (v0.w + v1.w) + (v2.w + v3.w);
        }
        for (; i + 4 <= cnt; i += 4) {
            int s0 = g_csr[base + i + sub];
            float4 v0 = *(const float4*)&g_p[(size_t)s0 * DD + quad * 4];
            a4.x += v0.x; a4.y += v0.y; a4.z += v0.z; a4.w += v0.w;
        }
        if (i + sub < cnt) {
            int s0 = g_csr[base + i + sub];
            float4 v0 = *(const float4*)&g_p[(size_t)s0 * DD + quad * 4];
            a4.x += v0.x; a4.y += v0.y; a4.z += v0.z; a4.w += v0.w;
        }
        // reduce across the 4 edge subgroups
        a4.x += __shfl_xor_sync(FULL, a4.x, 8);
        a4.y += __shfl_xor_sync(FULL, a4.y, 8);
        a4.z += __shfl_xor_sync(FULL, a4.z, 8);
        a4.w += __shfl_xor_sync(FULL, a4.w, 8);
        a4.x += __shfl_xor_sync(FULL, a4.x, 16);
        a4.y += __shfl_xor_sync(FULL, a4.y, 16);
        a4.z += __shfl_xor_sync(FULL, a4.z, 16);
        a4.w += __shfl_xor_sync(FULL, a4.w, 16);

        // self term + bias + relu
        float4 self = *(const float4*)&g_p[(size_t)n * DD + quad * 4];
        const float4 b4 = *(const float4*)&sba4[quad * 4];
        float4 t4;
        t4.x = fmaxf(a4.x + self.x + b4.x, 0.f);
        t4.y = fmaxf(a4.y + self.y + b4.y, 0.f);
        t4.z = fmaxf(a4.z + self.z + b4.z, 0.f);
        t4.w = fmaxf(a4.w + self.w + b4.w, 0.f);

        __syncwarp();                 // previous iteration's sT readers done
        if (lane < 8) *(float4*)&sT[w][lane * 4] = t4;
        __syncwarp();

        // matvec: hv(lane) = bb + sum_k t[k]*Wb[k][lane] via broadcast LDS.128
        float hv = bbl;
#pragma unroll
        for (int k4 = 0; k4 < 8; k4++) {
            float4 tv = *(const float4*)&sT[w][k4 * 4];
            hv = fmaf(tv.x, wb[k4 * 4 + 0], hv);
            hv = fmaf(tv.y, wb[k4 * 4 + 1], hv);
            hv = fmaf(tv.z, wb[k4 * 4 + 2], hv);
            hv = fmaf(tv.w, wb[k4 * 4 + 3], hv);
        }
        hv = fmaxf(hv, 0.f);
        g_h[(size_t)n * DD + lane] = hv;
        ls += hv;
        lq += hv * hv;
    }

    atomicAdd(&sS[lane], ls);
    atomicAdd(&sQ[lane], lq);
    __syncthreads();
    if (w == 0) {
        float* st = g_stats + stats_layer * 2 * DD;
        atomicAdd(&st[lane], sS[lane]);
        atomicAdd(&st[DD + lane], sQ[lane]);
    }
}

// ---------------------------------------------------------------------------
// Segmented global add pool (batch is sorted)
__global__ __launch_bounds__(256) void k_pool(const int* __restrict__ batch,
                                              const float* __restrict__ gamma,
                                              const float* __restrict__ beta) {
    __shared__ float sS[DD], sC[DD];
    const float* st = g_stats + 4 * 2 * DD;
    if (threadIdx.x < DD) {
        float m = st[threadIdx.x] * (1.f / NN);
        float v = st[DD + threadIdx.x] * (1.f / NN) - m * m;
        float s = gamma[threadIdx.x] * rsqrtf(v + BN_EPS);
        sS[threadIdx.x] = s;
        sC[threadIdx.x] = beta[threadIdx.x] - m * s;
    }
    __syncthreads();

    int lane = threadIdx.x & 31;
    int w = threadIdx.x >> 5;
    int wid = blockIdx.x * 8 + w;
    int n0 = wid * 64;
    if (n0 >= NN) return;
    int n1 = min(n0 + 64, NN);

    float s = sS[lane], c = sC[lane];
    int curg = __ldg(&batch[n0]);
    float acc = 0.f;
    for (int n = n0; n < n1; n++) {
        int g = __ldg(&batch[n]);
        if (g != curg) {
            atomicAdd(&g_pooled[curg * DD + lane], acc);
            acc = 0.f;
            curg = g;
        }
        acc = fmaf(s, g_h[(size_t)n * DD + lane], acc + c);
    }
    atomicAdd(&g_pooled[curg * DD + lane], acc);
}

// ---------------------------------------------------------------------------
// Head: relu(pooled@fc1+b1) @ fc2 + b2, log_softmax. One thread per graph.
__global__ __launch_bounds__(256) void k_head(const float* __restrict__ fc1w,
                                              const float* __restrict__ fc1b,
                                              const float* __restrict__ fc2w,
                                              const float* __restrict__ fc2b,
                                              float* __restrict__ out) {
    __shared__ float sW1[DD * DD], sW2[DD * CC], sb1[DD], sb2[CC];
    for (int i = threadIdx.x; i < DD * DD; i += 256) sW1[i] = fc1w[i];
    for (int i = threadIdx.x; i < DD * CC; i += 256) sW2[i] = fc2w[i];
    if (threadIdx.x < DD) sb1[threadIdx.x] = fc1b[threadIdx.x];
    if (threadIdx.x < CC) sb2[threadIdx.x] = fc2b[threadIdx.x];
    __syncthreads();

    int g = blockIdx.x * 256 + threadIdx.x;
    if (g >= GG) return;

    float pv[DD];
    const float4* pr = (const float4*)&g_pooled[g * DD];
#pragma unroll
    for (int j4 = 0; j4 < 8; j4++) {
        float4 t = pr[j4];
        pv[j4 * 4 + 0] = t.x; pv[j4 * 4 + 1] = t.y;
        pv[j4 * 4 + 2] = t.z; pv[j4 * 4 + 3] = t.w;
    }
    float u[DD];
#pragma unroll
    for (int j = 0; j < DD; j++) u[j] = sb1[j];
#pragma unroll 4
    for (int k = 0; k < DD; k++) {
        float pk = pv[k];
#pragma unroll
        for (int j = 0; j < DD; j++) u[j] += pk * sW1[k * DD + j];
    }
#pragma unroll
    for (int j = 0; j < DD; j++) u[j] = fmaxf(u[j], 0.f);

    float lg[CC];
#pragma unroll
    for (int c = 0; c < CC; c++) lg[c] = sb2[c];
#pragma unroll 4
    for (int j = 0; j < DD; j++) {
        float uj = u[j];
#pragma unroll
        for (int c = 0; c < CC; c++) lg[c] += uj * sW2[j * CC + c];
    }
    float mx = lg[0];
#pragma unroll
    for (int c = 1; c < CC; c++) mx = fmaxf(mx, lg[c]);
    float se = 0.f;
#pragma unroll
    for (int c = 0; c < CC; c++) se += expf(lg[c] - mx);
    float lse = mx + logf(se);
#pragma unroll
    for (int c = 0; c < CC; c++) out[g * CC + c] = lg[c] - lse;
}

// ---------------------------------------------------------------------------
extern "C" void kernel_launch(void* const* d_in, const int* in_sizes, int n_in,
                              void* d_out, int out_size) {
    const float* x     = (const float*)d_in[0];
    const int*   ei    = (const int*)d_in[1];
    const int*   batch = (const int*)d_in[2];
    const float* W1a   = (const float*)d_in[3];
    const float* b1a   = (const float*)d_in[4];
    const float* W1b   = (const float*)d_in[5];
    const float* b1b   = (const float*)d_in[6];
    const float* Wa    = (const float*)d_in[7];
    const float* ba    = (const float*)d_in[8];
    const float* Wb    = (const float*)d_in[9];
    const float* bb    = (const float*)d_in[10];
    const float* gamma = (const float*)d_in[11];
    const float* beta  = (const float*)d_in[12];
    const float* fc1w  = (const float*)d_in[13];
    const float* fc1b  = (const float*)d_in[14];
    const float* fc2w  = (const float*)d_in[15];
    const float* fc2b  = (const float*)d_in[16];
    float* out = (float*)d_out;

    const int* src = ei;        // row 0
    const int* dst = ei + EE;   // row 1

    const int NB = (NN + 255) / 256;          // 391
    const int EB = EE / 256;                  // 6250
    const int SCAN_BLK = (NN + 1023) / 1024;  // 98
    const int GMA_BLK = 1480;
    const int PB = ((NN + 63) / 64 + 7) / 8;

    // Layer-1 projection + scratch init (independent of CSR build)
    k_proj1<<<NB, 256>>>(x, W1a);

    // CSR build (dst-grouped edge list)
    k_hist<<<EB, 256>>>(dst);
    k_scan1<<<SCAN_BLK, 256>>>();
    k_scan23<<<NB, 256>>>();
    k_fill<<<EB, 256>>>(src, dst);

    // Layer 1 gather+MLP+stats
    k_gma<<<GMA_BLK, 256>>>(b1a, W1b, b1b, 0);

    // Layers 2-5 (BN folded into projection)
    for (int i = 0; i < 4; i++) {
        k_proj<<<NB, 256>>>(i, gamma + i * DD, beta + i * DD, Wa + i * DD * DD);
        k_gma<<<GMA_BLK, 256>>>(ba + i * DD, Wb + i * DD * DD, bb + i * DD, i + 1);
    }

    // Pool (applies BN layer 5) + head
    k_pool<<<PB, 256>>>(batch, gamma + 4 * DD, beta + 4 * DD);
    k_head<<<(GG + 255) / 256, 256>>>(fc1w, fc1b, fc2w, fc2b, out);
}